// round 11
// baseline (speedup 1.0000x reference)
#include <cuda_runtime.h>
#include <cuda_fp16.h>
#include <math.h>
#include <cstdint>

// ContactMapHead via single-pass fp16 HMMA GEMMs (tcgen05 rejected by sm_103
// PTX target). fp16 products are exact in the fp32 accumulator.
//   h      = relu(hs @ W^T + b)        hs:[8192,1024] W:[256,1024]
//   scores = (h @ h^T) * s + c         per batch of 4, S=2048
// R10: W fp32->fp16 conversion ALSO fused into proj (B path LDG->cvt->STS,
// register prefetch, 2-slot, single sync per chunk) — no standalone convert
// kernel at all. Scores identical to validated R8. No register caps (R9
// regression reverted).

#define B_    4
#define S_    2048
#define D_    1024
#define P_    256
#define MROWS 8192

#define BK    32

// ---- proj smem: 2 slots of (64 A rows + 128 B rows) x 80B ----
#define PROJ_ROWB   80
#define PROJ_STAGE  ((64 + 128) * PROJ_ROWB)   // 15360
#define PROJ_SMEM   (2 * PROJ_STAGE)           // 30720

// ---- scores smem: BK=64, 2 stages, ROWB=144 ----
#define SC_ROWB    144
#define SC_ASIZE   (64 * SC_ROWB)              // 9216
#define SC_STAGE   ((64 + 128) * SC_ROWB)      // 27648
#define SC_SMEM    (2 * SC_STAGE)              // 55296 (epi 64*132*4=33792 fits)

// ---------------- scratch ----------------
__device__ unsigned short g_h16[(size_t)MROWS * P_];

// ---------------- asm helpers ----------------
__device__ __forceinline__ uint32_t smem_u32(const void* p) {
    uint32_t a;
    asm("{ .reg .u64 t; cvta.to.shared.u64 t, %1; cvt.u32.u64 %0, t; }" : "=r"(a) : "l"(p));
    return a;
}
__device__ __forceinline__ void cpa16(uint32_t s, const void* g) {
    asm volatile("cp.async.cg.shared.global [%0], [%1], 16;" :: "r"(s), "l"(g));
}
#define CP_COMMIT() asm volatile("cp.async.commit_group;" ::: "memory")
#define CP_WAIT1()  asm volatile("cp.async.wait_group 1;" ::: "memory")
#define CP_WAIT0()  asm volatile("cp.async.wait_group 0;" ::: "memory")

#define LDMX4(r, addr) \
    asm volatile("ldmatrix.sync.aligned.m8n8.x4.shared.b16 {%0,%1,%2,%3}, [%4];" \
        : "=r"((r)[0]), "=r"((r)[1]), "=r"((r)[2]), "=r"((r)[3]) : "r"(addr))

#define MMA16816(d, a, b0, b1) \
    asm volatile("mma.sync.aligned.m16n8k16.row.col.f32.f16.f16.f32 " \
        "{%0,%1,%2,%3},{%4,%5,%6,%7},{%8,%9},{%0,%1,%2,%3};" \
        : "+f"((d)[0]), "+f"((d)[1]), "+f"((d)[2]), "+f"((d)[3]) \
        : "r"((a)[0]), "r"((a)[1]), "r"((a)[2]), "r"((a)[3]), "r"(b0), "r"(b1))

#define STS128(addr, v) \
    asm volatile("st.shared.v4.b32 [%0], {%1,%2,%3,%4};" \
        :: "r"(addr), "r"((v).x), "r"((v).y), "r"((v).z), "r"((v).w))

__device__ __forceinline__ uint4 cvt8(float4 x, float4 y) {
    __half2 h0 = __floats2half2_rn(x.x, x.y);
    __half2 h1 = __floats2half2_rn(x.z, x.w);
    __half2 h2 = __floats2half2_rn(y.x, y.y);
    __half2 h3 = __floats2half2_rn(y.z, y.w);
    uint4 v;
    v.x = *(uint32_t*)&h0; v.y = *(uint32_t*)&h1;
    v.z = *(uint32_t*)&h2; v.w = *(uint32_t*)&h3;
    return v;
}

// ---------------- proj: h = relu(hs@W^T + b) -> h fp16, fully fused convert --
// 64x128 tile, 8 warps 2(M)x4(N). Both operands: LDG fp32 -> cvt -> STS,
// 2-slot double buffer with register prefetch; ONE __syncthreads per chunk.
__global__ __launch_bounds__(256) void proj_gemm_kernel(
    const float* __restrict__ hs, const float* __restrict__ W,
    const float* __restrict__ bias)
{
    extern __shared__ char smem[];
    uint32_t sbase = smem_u32(smem);
    const int tid = threadIdx.x, lane = tid & 31, w = tid >> 5;
    const int wm = w & 1, wn = w >> 1;
    const int row0 = blockIdx.y * 64, col0 = blockIdx.x * 128;
    const int NC = D_ / BK;   // 32

    // A: row tid>>2 (0..63), 8 floats at col (tid&3)*8
    const float* aptr = hs + (size_t)(row0 + (tid >> 2)) * D_ + (tid & 3) * 8;
    const uint32_t asts = (tid >> 2) * PROJ_ROWB + (tid & 3) * 16;
    // B: W row tid>>1 (0..127), 16 floats at col (tid&1)*16
    const float* bptr = W + (size_t)(col0 + (tid >> 1)) * D_ + (tid & 1) * 16;
    const uint32_t bsts = 64 * PROJ_ROWB + (tid >> 1) * PROJ_ROWB + (tid & 1) * 32;

    // prologue: chunk 0 through registers into slot 0
    float4 a0 = ((const float4*)aptr)[0];
    float4 a1 = ((const float4*)aptr)[1];
    float4 b0 = ((const float4*)bptr)[0];
    float4 b1 = ((const float4*)bptr)[1];
    float4 b2 = ((const float4*)bptr)[2];
    float4 b3 = ((const float4*)bptr)[3];
    {
        uint4 va = cvt8(a0, a1);
        STS128(sbase + asts, va);
        uint4 vb0 = cvt8(b0, b1), vb1 = cvt8(b2, b3);
        STS128(sbase + bsts, vb0);
        STS128(sbase + bsts + 16, vb1);
    }

    float acc[2][4][4] = {};
    const uint32_t aoffm = (wm * 32 + (lane & 15)) * PROJ_ROWB + (lane >> 4) * 16;
    const uint32_t boff  = 64 * PROJ_ROWB + (wn * 32 + (lane & 15)) * PROJ_ROWB + (lane >> 4) * 16;

    for (int c = 0; c < NC; c++) {
        if (c + 1 < NC) {                         // prefetch next chunk (LDG)
            const float4* ap = (const float4*)(aptr + (c + 1) * BK);
            a0 = ap[0]; a1 = ap[1];
            const float4* bp = (const float4*)(bptr + (c + 1) * BK);
            b0 = bp[0]; b1 = bp[1]; b2 = bp[2]; b3 = bp[3];
        }
        __syncthreads();   // slot c&1 stores visible; compute c-1 done -> slot (c+1)&1 free
        if (c + 1 < NC) {                         // cvt + STS into other slot
            uint32_t st = sbase + ((c + 1) & 1) * PROJ_STAGE;
            uint4 va = cvt8(a0, a1);
            STS128(st + asts, va);
            uint4 vb0 = cvt8(b0, b1), vb1 = cvt8(b2, b3);
            STS128(st + bsts, vb0);
            STS128(st + bsts + 16, vb1);
        }

        uint32_t st = sbase + (c & 1) * PROJ_STAGE;
#pragma unroll
        for (int k16 = 0; k16 < 2; k16++) {
            uint32_t a[2][4], b[2][4];
#pragma unroll
            for (int mt = 0; mt < 2; mt++)
                LDMX4(a[mt], st + aoffm + mt * 16 * PROJ_ROWB + k16 * 32);
#pragma unroll
            for (int np = 0; np < 2; np++)
                LDMX4(b[np], st + boff + np * 16 * PROJ_ROWB + k16 * 32);
#pragma unroll
            for (int mt = 0; mt < 2; mt++)
#pragma unroll
                for (int nt = 0; nt < 4; nt++)
                    MMA16816(acc[mt][nt], a[mt], b[nt >> 1][nt & 1], b[nt >> 1][(nt & 1) + 2]);
        }
    }

    // epilogue: bias + relu -> h fp16 (coalesced pairs)
    uint32_t* hh = (uint32_t*)g_h16;
#pragma unroll
    for (int nt = 0; nt < 4; nt++) {
        int col = col0 + wn * 32 + nt * 8 + (lane & 3) * 2;
        float bb0 = bias[col], bb1 = bias[col + 1];
#pragma unroll
        for (int mt = 0; mt < 2; mt++) {
            int r0 = row0 + wm * 32 + mt * 16 + (lane >> 2);
#pragma unroll
            for (int hh2 = 0; hh2 < 2; hh2++) {
                int r = r0 + hh2 * 8;
                float v0 = fmaxf(acc[mt][nt][hh2 * 2 + 0] + bb0, 0.f);
                float v1 = fmaxf(acc[mt][nt][hh2 * 2 + 1] + bb1, 0.f);
                __half2 p = __floats2half2_rn(v0, v1);
                hh[((size_t)r * P_ + col) >> 1] = *(uint32_t*)&p;
            }
        }
    }
}

// ---------------- scores: 64x128 tiles, BK=64, 2-stage, tri+mirror ----------
// Per batch: col tiles j=0..15 (128 wide), row tiles i=2j..31 (64 tall).
// t = i-2j; t<2 -> inside diagonal 128-block (direct only); t>=2 -> + mirror.
__global__ __launch_bounds__(256) void scores_gemm_kernel(
    const float* __restrict__ clf_w, const float* __restrict__ clf_b,
    float* __restrict__ out)
{
    extern __shared__ char smem[];
    uint32_t sbase = smem_u32(smem);
    const int tid = threadIdx.x, lane = tid & 31, w = tid >> 5;
    const int wm = w & 1, wn = w >> 1;

    int t = blockIdx.x, j = 0;
    while (t >= 32 - 2 * j) { t -= 32 - 2 * j; j++; }
    const int i = 2 * j + t;
    const int rows0 = i * 64, cols0 = j * 128;
    const bool diag = (t < 2);

    const unsigned short* hb = g_h16 + (size_t)blockIdx.z * S_ * P_;
    float* outb = out + (size_t)blockIdx.z * S_ * S_;

    auto load_chunk = [&](int slot, int koff) {
        uint32_t sA = sbase + slot * SC_STAGE;
        uint32_t sB = sA + SC_ASIZE;
#pragma unroll
        for (int q = 0; q < 2; q++) {
            int ch = tid + q * 256;
            int r = ch >> 3, c16 = ch & 7;
            cpa16(sA + r * SC_ROWB + c16 * 16,
                  hb + (size_t)(rows0 + r) * P_ + koff + c16 * 8);
        }
#pragma unroll
        for (int q = 0; q < 4; q++) {
            int ch = tid + q * 256;
            int r = ch >> 3, c16 = ch & 7;
            cpa16(sB + r * SC_ROWB + c16 * 16,
                  hb + (size_t)(cols0 + r) * P_ + koff + c16 * 8);
        }
    };

    load_chunk(0, 0);
    CP_COMMIT();

    float acc[2][4][4] = {};
    const uint32_t aoffm = (wm * 32 + (lane & 15)) * SC_ROWB + (lane >> 4) * 16;
    const uint32_t boff  = (wn * 32 + (lane & 15)) * SC_ROWB + (lane >> 4) * 16;
    const int NC = P_ / 64;   // 4

    for (int c = 0; c < NC; c++) {
        if (c + 1 < NC) {
            load_chunk((c + 1) & 1, (c + 1) * 64);
            CP_COMMIT();
            CP_WAIT1();
        } else {
            CP_WAIT0();
        }
        __syncthreads();

        uint32_t sA = sbase + (c & 1) * SC_STAGE;
        uint32_t sB = sA + SC_ASIZE;
#pragma unroll
        for (int k16 = 0; k16 < 4; k16++) {
            uint32_t a[2][4], b[2][4];
#pragma unroll
            for (int mt = 0; mt < 2; mt++)
                LDMX4(a[mt], sA + aoffm + mt * 16 * SC_ROWB + k16 * 32);
#pragma unroll
            for (int np = 0; np < 2; np++)
                LDMX4(b[np], sB + boff + np * 16 * SC_ROWB + k16 * 32);
#pragma unroll
            for (int mt = 0; mt < 2; mt++)
#pragma unroll
                for (int nt = 0; nt < 4; nt++)
                    MMA16816(acc[mt][nt], a[mt], b[nt >> 1][nt & 1], b[nt >> 1][(nt & 1) + 2]);
        }
        __syncthreads();
    }

    const float sw = clf_w[0], cb = clf_b[0];
    float* sep = (float*)smem;   // [64][132]

#pragma unroll
    for (int mt = 0; mt < 2; mt++)
#pragma unroll
        for (int nt = 0; nt < 4; nt++) {
            int lr = wm * 32 + mt * 16 + (lane >> 2);
            int lc = wn * 32 + nt * 8 + (lane & 3) * 2;
            sep[lr * 132 + lc]           = acc[mt][nt][0];
            sep[lr * 132 + lc + 1]       = acc[mt][nt][1];
            sep[(lr + 8) * 132 + lc]     = acc[mt][nt][2];
            sep[(lr + 8) * 132 + lc + 1] = acc[mt][nt][3];
        }
    __syncthreads();

    // direct block: 64 rows x 128 cols
#pragma unroll
    for (int pass = 0; pass < 8; pass++) {
        int r = pass * 8 + w;
        float4 v = *(const float4*)(sep + r * 132 + lane * 4);
        v.x = fmaf(v.x, sw, cb); v.y = fmaf(v.y, sw, cb);
        v.z = fmaf(v.z, sw, cb); v.w = fmaf(v.w, sw, cb);
        *(float4*)&outb[(size_t)(rows0 + r) * S_ + cols0 + lane * 4] = v;
    }
    // mirrored block: 128 rows x 64 cols
    if (!diag) {
#pragma unroll
        for (int pass = 0; pass < 8; pass++) {
            int c  = pass * 16 + w * 2 + (lane >> 4);
            int rg = lane & 15;
            float4 v;
            v.x = fmaf(sep[(rg * 4 + 0) * 132 + c], sw, cb);
            v.y = fmaf(sep[(rg * 4 + 1) * 132 + c], sw, cb);
            v.z = fmaf(sep[(rg * 4 + 2) * 132 + c], sw, cb);
            v.w = fmaf(sep[(rg * 4 + 3) * 132 + c], sw, cb);
            *(float4*)&outb[(size_t)(cols0 + c) * S_ + rows0 + rg * 4] = v;
        }
    }
}

// ---------------- launch ----------------
extern "C" void kernel_launch(void* const* d_in, const int* in_sizes, int n_in,
                              void* d_out, int out_size)
{
    const float* hs     = (const float*)d_in[0];
    const float* proj_w = (const float*)d_in[1];
    const float* proj_b = (const float*)d_in[2];
    const float* clf_w  = (const float*)d_in[3];
    const float* clf_b  = (const float*)d_in[4];
    float* out = (float*)d_out;

    cudaFuncSetAttribute(proj_gemm_kernel,
                         cudaFuncAttributeMaxDynamicSharedMemorySize, PROJ_SMEM);
    cudaFuncSetAttribute(scores_gemm_kernel,
                         cudaFuncAttributeMaxDynamicSharedMemorySize, SC_SMEM);

    {   // projection + relu -> h fp16 (hs AND W converted in-kernel)
        dim3 grid(P_ / 128, MROWS / 64);    // (2, 128) = 256 CTAs
        proj_gemm_kernel<<<grid, 256, PROJ_SMEM>>>(hs, proj_w, proj_b);
    }
    {   // symmetric scores: 64x128 tiles, BK=64, 272 tiles/batch
        dim3 grid(272, 1, B_);              // 1088 CTAs
        scores_gemm_kernel<<<grid, 256, SC_SMEM>>>(clf_w, clf_b, out);
    }
}